// round 2
// baseline (speedup 1.0000x reference)
#include <cuda_runtime.h>
#include <cuda_bf16.h>

#define DD 128
#define TILE_M 64
#define KC 32

// 51.2 MB scratch for support1 = X @ W1 (static device array: allowed, no alloc)
__device__ float g_s1[100000 * DD];

// Fused dual GEMM: out = X@W0 + bias,  g_s1 = X@W1
// Block: 256 threads computes a 64x128 output tile for BOTH weight matrices.
// Thread (tx in 0..15, ty in 0..15) computes rows [ty*4, ty*4+4) x cols [tx*8, tx*8+8).
__global__ __launch_bounds__(256) void gemm2_kernel(
    const float* __restrict__ X, const float* __restrict__ W0,
    const float* __restrict__ W1, const float* __restrict__ bias,
    float* __restrict__ out, int N)
{
    __shared__ float Xs[TILE_M][KC + 4];   // pad to 36 floats/row (16B-aligned)
    __shared__ float W0s[KC][DD];
    __shared__ float W1s[KC][DD];

    const int tid = threadIdx.x;
    const int tx = tid & 15;
    const int ty = tid >> 4;
    const int row0 = blockIdx.x * TILE_M;

    float acc0[4][8];
    float acc1[4][8];
#pragma unroll
    for (int i = 0; i < 4; i++)
#pragma unroll
        for (int j = 0; j < 8; j++) { acc0[i][j] = 0.f; acc1[i][j] = 0.f; }

    for (int kc = 0; kc < DD; kc += KC) {
        __syncthreads();
        // Load X tile: 64 rows x 32 cols = 512 float4, 2 per thread
#pragma unroll
        for (int i = 0; i < 2; i++) {
            int idx = tid + i * 256;
            int r = idx >> 3;        // 0..63
            int q = idx & 7;         // 0..7  (float4 col group)
            int gr = row0 + r;
            if (gr >= N) gr = N - 1; // clamp (stores are guarded)
            *(float4*)&Xs[r][q * 4] =
                *(const float4*)&X[(long long)gr * DD + kc + q * 4];
        }
        // Load W0/W1 chunks: 32 rows x 128 cols = 1024 float4 each, 4 per thread
#pragma unroll
        for (int i = 0; i < 4; i++) {
            int idx = tid + i * 256;
            int r = idx >> 5;        // 0..31
            int q = idx & 31;        // 0..31 (float4 col group)
            *(float4*)&W0s[r][q * 4] = *(const float4*)&W0[(kc + r) * DD + q * 4];
            *(float4*)&W1s[r][q * 4] = *(const float4*)&W1[(kc + r) * DD + q * 4];
        }
        __syncthreads();

#pragma unroll
        for (int k = 0; k < KC; k++) {
            float a[4];
#pragma unroll
            for (int i = 0; i < 4; i++) a[i] = Xs[ty * 4 + i][k];
            float4 b0a = *(float4*)&W0s[k][tx * 8];
            float4 b0b = *(float4*)&W0s[k][tx * 8 + 4];
            float4 b1a = *(float4*)&W1s[k][tx * 8];
            float4 b1b = *(float4*)&W1s[k][tx * 8 + 4];
#pragma unroll
            for (int i = 0; i < 4; i++) {
                acc0[i][0] += a[i] * b0a.x; acc0[i][1] += a[i] * b0a.y;
                acc0[i][2] += a[i] * b0a.z; acc0[i][3] += a[i] * b0a.w;
                acc0[i][4] += a[i] * b0b.x; acc0[i][5] += a[i] * b0b.y;
                acc0[i][6] += a[i] * b0b.z; acc0[i][7] += a[i] * b0b.w;
                acc1[i][0] += a[i] * b1a.x; acc1[i][1] += a[i] * b1a.y;
                acc1[i][2] += a[i] * b1a.z; acc1[i][3] += a[i] * b1a.w;
                acc1[i][4] += a[i] * b1b.x; acc1[i][5] += a[i] * b1b.y;
                acc1[i][6] += a[i] * b1b.z; acc1[i][7] += a[i] * b1b.w;
            }
        }
    }

    float4 bq0 = *(const float4*)&bias[tx * 8];
    float4 bq1 = *(const float4*)&bias[tx * 8 + 4];

#pragma unroll
    for (int i = 0; i < 4; i++) {
        int gr = row0 + ty * 4 + i;
        if (gr < N) {
            long long base = (long long)gr * DD + tx * 8;
            float4 o0 = make_float4(acc0[i][0] + bq0.x, acc0[i][1] + bq0.y,
                                    acc0[i][2] + bq0.z, acc0[i][3] + bq0.w);
            float4 o1 = make_float4(acc0[i][4] + bq1.x, acc0[i][5] + bq1.y,
                                    acc0[i][6] + bq1.z, acc0[i][7] + bq1.w);
            *(float4*)&out[base]     = o0;
            *(float4*)&out[base + 4] = o1;
            *(float4*)&g_s1[base]     = make_float4(acc1[i][0], acc1[i][1], acc1[i][2], acc1[i][3]);
            *(float4*)&g_s1[base + 4] = make_float4(acc1[i][4], acc1[i][5], acc1[i][6], acc1[i][7]);
        }
    }
}

// One warp per edge: gather 512B row of support1 (L2-resident), scale,
// 128-bit vector reduction into out (no return value, no read-modify-write trip).
// edge_index is int32 (JAX x64 disabled downcasts the declared int64).
__global__ __launch_bounds__(256) void edge_kernel(
    const int* __restrict__ ei, const float* __restrict__ ev,
    float* __restrict__ out, int E)
{
    long long t = (long long)blockIdx.x * blockDim.x + threadIdx.x;
    int e = (int)(t >> 5);
    if (e >= E) return;
    int lane = threadIdx.x & 31;

    int src = __ldg(&ei[e]);
    int dst = __ldg(&ei[E + e]);
    float a = __ldg(&ev[e]);

    float4 v = *(const float4*)(g_s1 + (long long)src * DD + lane * 4);
    v.x *= a; v.y *= a; v.z *= a; v.w *= a;

    float* p = out + (long long)dst * DD + lane * 4;
    asm volatile("red.global.add.v4.f32 [%0], {%1,%2,%3,%4};"
                 :: "l"(p), "f"(v.x), "f"(v.y), "f"(v.z), "f"(v.w)
                 : "memory");
}

extern "C" void kernel_launch(void* const* d_in, const int* in_sizes, int n_in,
                              void* d_out, int out_size)
{
    const float* X    = (const float*)d_in[0];   // [N,128] f32
    const int*   ei   = (const int*)d_in[1];     // [2,E] int32 (see note)
    const float* ev   = (const float*)d_in[2];   // [E] f32
    const float* W0   = (const float*)d_in[3];   // [128,128] f32
    const float* W1   = (const float*)d_in[4];   // [128,128] f32
    const float* bias = (const float*)d_in[5];   // [128] f32
    float* out = (float*)d_out;

    int N = in_sizes[0] / DD;
    int E = in_sizes[2];

    // Kernel 1: out = X@W0 + bias (fully writes out), g_s1 = X@W1
    gemm2_kernel<<<(N + TILE_M - 1) / TILE_M, 256>>>(X, W0, W1, bias, out, N);

    // Kernel 2: out[dst] += ev[e] * g_s1[src]  (one warp per edge)
    long long threads = (long long)E * 32;
    int blocks = (int)((threads + 255) / 256);
    edge_kernel<<<blocks, 256>>>(ei, ev, out, E);
}

// round 5
// speedup vs baseline: 1.0388x; 1.0388x over previous
#include <cuda_runtime.h>
#include <cuda_bf16.h>

#define DD 128
#define TILE_M 64
#define KC 32

// 51.2 MB scratch for support1 = X @ W1 (static device array: allowed, no alloc)
__device__ float g_s1[100000 * DD];

// ---------------------------------------------------------------------------
// Single-matrix 64x128 GEMM tile. EPI=0: plain store to dst. EPI=1: red.add.
// 256 threads: tx in 0..15 (8 cols each), ty in 0..15 (4 rows each).
// ---------------------------------------------------------------------------
template <int EPI>
__device__ __forceinline__ void gemm_tile(
    const float* __restrict__ X, const float* __restrict__ W,
    float* __restrict__ dst, int N, int bid)
{
    __shared__ float Xs[TILE_M][KC + 4];
    __shared__ float Ws[KC][DD];

    const int tid = threadIdx.x;
    const int tx = tid & 15;
    const int ty = tid >> 4;
    const int row0 = bid * TILE_M;

    float acc[4][8];
#pragma unroll
    for (int i = 0; i < 4; i++)
#pragma unroll
        for (int j = 0; j < 8; j++) acc[i][j] = 0.f;

    for (int kc = 0; kc < DD; kc += KC) {
        __syncthreads();
        // X tile: 64 rows x 32 cols = 512 float4, 2 per thread
#pragma unroll
        for (int i = 0; i < 2; i++) {
            int idx = tid + i * 256;
            int r = idx >> 3;
            int q = idx & 7;
            int gr = row0 + r;
            if (gr >= N) gr = N - 1;
            *(float4*)&Xs[r][q * 4] =
                *(const float4*)&X[(long long)gr * DD + kc + q * 4];
        }
        // W chunk: 32 rows x 128 cols = 1024 float4, 4 per thread
#pragma unroll
        for (int i = 0; i < 4; i++) {
            int idx = tid + i * 256;
            int r = idx >> 5;
            int q = idx & 31;
            *(float4*)&Ws[r][q * 4] = *(const float4*)&W[(kc + r) * DD + q * 4];
        }
        __syncthreads();

#pragma unroll
        for (int k = 0; k < KC; k++) {
            float a[4];
#pragma unroll
            for (int i = 0; i < 4; i++) a[i] = Xs[ty * 4 + i][k];
            float4 ba = *(float4*)&Ws[k][tx * 8];
            float4 bb = *(float4*)&Ws[k][tx * 8 + 4];
#pragma unroll
            for (int i = 0; i < 4; i++) {
                acc[i][0] += a[i] * ba.x; acc[i][1] += a[i] * ba.y;
                acc[i][2] += a[i] * ba.z; acc[i][3] += a[i] * ba.w;
                acc[i][4] += a[i] * bb.x; acc[i][5] += a[i] * bb.y;
                acc[i][6] += a[i] * bb.z; acc[i][7] += a[i] * bb.w;
            }
        }
    }

#pragma unroll
    for (int i = 0; i < 4; i++) {
        int gr = row0 + ty * 4 + i;
        if (gr < N) {
            long long base = (long long)gr * DD + tx * 8;
            if (EPI == 0) {
                *(float4*)&dst[base] =
                    make_float4(acc[i][0], acc[i][1], acc[i][2], acc[i][3]);
                *(float4*)&dst[base + 4] =
                    make_float4(acc[i][4], acc[i][5], acc[i][6], acc[i][7]);
            } else {
                float* p0 = dst + base;
                float* p1 = dst + base + 4;
                asm volatile("red.global.add.v4.f32 [%0], {%1,%2,%3,%4};"
                             :: "l"(p0), "f"(acc[i][0]), "f"(acc[i][1]),
                                "f"(acc[i][2]), "f"(acc[i][3]) : "memory");
                asm volatile("red.global.add.v4.f32 [%0], {%1,%2,%3,%4};"
                             :: "l"(p1), "f"(acc[i][4]), "f"(acc[i][5]),
                                "f"(acc[i][6]), "f"(acc[i][7]) : "memory");
            }
        }
    }
}

// ---------------------------------------------------------------------------
// k1: blocks [0,G) compute g_s1 = X@W1. Blocks [G, G+ZB) fill out with bias.
// ---------------------------------------------------------------------------
__global__ __launch_bounds__(256) void k1_kernel(
    const float* __restrict__ X, const float* __restrict__ W1,
    const float* __restrict__ bias, float* __restrict__ out,
    int N, int G, int ZB)
{
    if ((int)blockIdx.x < G) {
        gemm_tile<0>(X, W1, g_s1, N, blockIdx.x);
    } else {
        int zb = blockIdx.x - G;
        int tid = threadIdx.x;
        float4 bv = *(const float4*)&bias[(tid & 31) * 4];
        size_t total4 = (size_t)N * (DD / 4);
        for (size_t i = (size_t)zb * 256 + tid; i < total4;
             i += (size_t)ZB * 256)
            ((float4*)out)[i] = bv;   // stride multiple of 32 keeps col fixed
    }
}

// ---------------------------------------------------------------------------
// k2: blocks [0,G): out += X@W0 (red epilogue).
//     blocks [G,..): edge aggregation, one warp per 32-edge batch,
//     4-deep gather/red pipeline, red.add.v4 into out.
// ---------------------------------------------------------------------------
__global__ __launch_bounds__(256) void k2_kernel(
    const float* __restrict__ X, const float* __restrict__ W0,
    const int* __restrict__ ei, const float* __restrict__ ev,
    float* __restrict__ out, int N, int E, int G)
{
    if ((int)blockIdx.x < G) {
        gemm_tile<1>(X, W0, out, N, blockIdx.x);
        return;
    }

    const int lane = threadIdx.x & 31;
    int wglob = (blockIdx.x - G) * 8 + (threadIdx.x >> 5);
    int e0 = wglob * 32;
    if (e0 >= E) return;

    int e = e0 + lane;
    bool valid = e < E;
    int src = valid ? __ldg(&ei[e]) : 0;
    int dst = valid ? __ldg(&ei[E + e]) : 0;
    float a = valid ? __ldg(&ev[e]) : 0.f;   // a=0 => red adds 0: harmless

    const unsigned FULL = 0xffffffffu;
#pragma unroll 1
    for (int j0 = 0; j0 < 32; j0 += 4) {
        float4 v[4];
        int d[4];
        float s[4];
#pragma unroll
        for (int jj = 0; jj < 4; jj++) {
            int j = j0 + jj;
            int sj = __shfl_sync(FULL, src, j);
            d[jj] = __shfl_sync(FULL, dst, j);
            s[jj] = __shfl_sync(FULL, a, j);
            v[jj] = *(const float4*)(g_s1 + (size_t)sj * DD + lane * 4);
        }
#pragma unroll
        for (int jj = 0; jj < 4; jj++) {
            float4 t = v[jj];
            float sc = s[jj];
            t.x *= sc; t.y *= sc; t.z *= sc; t.w *= sc;
            float* p = out + (size_t)d[jj] * DD + lane * 4;
            asm volatile("red.global.add.v4.f32 [%0], {%1,%2,%3,%4};"
                         :: "l"(p), "f"(t.x), "f"(t.y), "f"(t.z), "f"(t.w)
                         : "memory");
        }
    }
}

extern "C" void kernel_launch(void* const* d_in, const int* in_sizes, int n_in,
                              void* d_out, int out_size)
{
    const float* X    = (const float*)d_in[0];   // [N,128] f32
    const int*   ei   = (const int*)d_in[1];     // [2,E] int32
    const float* ev   = (const float*)d_in[2];   // [E] f32
    const float* W0   = (const float*)d_in[3];   // [128,128] f32
    const float* W1   = (const float*)d_in[4];   // [128,128] f32
    const float* bias = (const float*)d_in[5];   // [128] f32
    float* out = (float*)d_out;

    int N = in_sizes[0] / DD;
    int E = in_sizes[2];

    int G = (N + TILE_M - 1) / TILE_M;           // 1563 GEMM tiles
    int ZB = 512;                                 // bias-fill blocks

    // k1: g_s1 = X@W1  ||  out = bias (broadcast fill)
    k1_kernel<<<G + ZB, 256>>>(X, W1, bias, out, N, G, ZB);

    // k2: out += X@W0 (red)  ||  out[dst] += ev*g_s1[src] (warp-batched edges)
    int EB = (E + 32 * 8 - 1) / (32 * 8);         // 6250 edge blocks
    k2_kernel<<<G + EB, 256>>>(X, W0, ei, ev, out, N, E, G);
}